// round 8
// baseline (speedup 1.0000x reference)
#include <cuda_runtime.h>
#include <cstdint>

#define NROWS 256
#define NDB   100000
#define DIM   64
#define XDIM  2048
#define NCLS  100
#define KSEL  1000
#define SPLIT 5
#define VP16  2500           // uint4 (8 u16) vectors per (row,part): 100000/8/5

// ---------------- static device scratch ----------------
__device__ float              g_outm[NROWS * DIM];
__device__ unsigned short     g_T16[(size_t)NROWS * NDB];               // 51.2 MB top-16 keys
__device__ unsigned long long g_cand[(size_t)NROWS * NDB / 8];          // 25.6 MB
__device__ unsigned int       g_hist[NROWS * 4096];
__device__ int                g_d1[NROWS];
__device__ int                g_need[NROWS];
__device__ unsigned int       g_candCnt[NROWS];
__device__ unsigned int       g_counts[NROWS * NCLS];

#define CANDCAP (NDB / 8)     // 12500 per row

// ---------------- helpers ----------------
__device__ __forceinline__ unsigned int mkey(float f) {
    unsigned int u = __float_as_uint(f);
    return (u & 0x80000000u) ? ~u : (u | 0x80000000u);
}
__device__ __forceinline__ void fma2(unsigned long long& d, unsigned long long a, unsigned long long b) {
    asm("fma.rn.f32x2 %0, %1, %2, %0;" : "+l"(d) : "l"(a), "l"(b));
}
__device__ __forceinline__ float f32lo(unsigned long long v) { return __uint_as_float((unsigned int)v); }
__device__ __forceinline__ float f32hi(unsigned long long v) { return __uint_as_float((unsigned int)(v >> 32)); }
__device__ __forceinline__ int probe_is64(const int* L) {
    int s = 0;
#pragma unroll
    for (int i = 1; i < 129; i += 2) s |= L[i];
    return (s == 0) ? 1 : 0;
}
__device__ __forceinline__ int ldlabel(const int* L, int n, int is64) {
    return is64 ? L[(size_t)2 * n] : L[n];
}

// ---------------- Z1/Z2: zero scratch ----------------
__global__ void __launch_bounds__(512) z1_hist() {
    ((uint4*)g_hist)[blockIdx.x * 512 + threadIdx.x] = make_uint4(0, 0, 0, 0);
}
__global__ void __launch_bounds__(512) z2_misc() {
    int i = blockIdx.x * 512 + threadIdx.x;
    if (i < NROWS * NCLS) g_counts[i] = 0u;
    if (i < NROWS) g_candCnt[i] = 0u;
}

// ---------------- K1: out = x @ W ----------------
__global__ void __launch_bounds__(256) k1_proj(const float* __restrict__ x,
                                               const float* __restrict__ W) {
    __shared__ __align__(16) float xs[XDIM];
    __shared__ float part[4][DIM];
    int b = blockIdx.x;
    const float4* xr = (const float4*)(x + (size_t)b * XDIM);
    for (int i = threadIdx.x; i < XDIM / 4; i += 256)
        ((float4*)xs)[i] = xr[i];
    __syncthreads();
    int j = threadIdx.x & 63;
    int p = threadIdx.x >> 6;
    const float* Wp = W + (size_t)(p * 512) * DIM + j;
    const float* xp = xs + p * 512;
    float a0 = 0.f, a1 = 0.f, a2 = 0.f, a3 = 0.f;
#pragma unroll 4
    for (int k = 0; k < 128; k++) {
        a0 += xp[k]       * Wp[(size_t)(k)       * DIM];
        a1 += xp[k + 128] * Wp[(size_t)(k + 128) * DIM];
        a2 += xp[k + 256] * Wp[(size_t)(k + 256) * DIM];
        a3 += xp[k + 384] * Wp[(size_t)(k + 384) * DIM];
    }
    part[p][j] = (a0 + a1) + (a2 + a3);
    __syncthreads();
    if (threadIdx.x < DIM)
        g_outm[b * DIM + threadIdx.x] =
            (part[0][threadIdx.x] + part[1][threadIdx.x]) +
            (part[2][threadIdx.x] + part[3][threadIdx.x]);
}

// ---------------- K2 v3: 128x128 tile; A lane-distinct, B broadcast ----------------
// smem: As float[64k][128rows] = 32KB ; Bs duplicated float2[64k][128cols] = 64KB
#define S_A 0
#define S_B 32768
#define S_K2TOT (32768 + 65536)

__global__ void __launch_bounds__(256, 2) k2_gemm(const float* __restrict__ codes) {
    extern __shared__ __align__(16) char smem[];
    float* As = (float*)(smem + S_A);                 // As[k*128 + row]
    float2* Bs2 = (float2*)(smem + S_B);              // Bs2[k*128 + col] = {f,f}
    const int tid  = threadIdx.x;
    const int wid  = tid >> 5;
    const int lane = tid & 31;
    const int row0 = blockIdx.x << 7;
    const int col0 = blockIdx.y << 7;

    // A tile: 128 rows x 64 k  (k-major, rows contiguous)
#pragma unroll
    for (int t = 0; t < 8; t++) {
        int e  = tid + t * 256;          // 0..2047
        int r  = e >> 4;                 // 0..127
        int k4 = (e & 15) << 2;
        float4 v = *(const float4*)&g_outm[((row0 + r) << 6) + k4];
#pragma unroll
        for (int j = 0; j < 4; j++)
            As[(k4 + j) * 128 + r] = (&v.x)[j];
    }
    // B tile: 128 cols x 64 k, duplicated pairs
#pragma unroll
    for (int t = 0; t < 8; t++) {
        int e  = tid + t * 256;
        int n  = e >> 4;                 // col 0..127
        int k4 = (e & 15) << 2;
        int gn = col0 + n;
        float4 v = make_float4(0.f, 0.f, 0.f, 0.f);
        if (gn < NDB) v = *(const float4*)&codes[((size_t)gn << 6) + k4];
#pragma unroll
        for (int j = 0; j < 4; j++) {
            float f = (&v.x)[j];
            Bs2[(k4 + j) * 128 + n] = make_float2(f, f);
        }
    }
    __syncthreads();

    // acc[h][c]: h=0 rows {2lane,2lane+1}, h=1 rows {64+2lane,...}; c = col wid*16+c
    unsigned long long acc0[16], acc1[16];
#pragma unroll
    for (int c = 0; c < 16; c++) { acc0[c] = 0ull; acc1[c] = 0ull; }

    const int cbase = wid << 4;
#pragma unroll 4
    for (int k = 0; k < 64; k++) {
        unsigned long long A0 = *(const unsigned long long*)&As[k * 128 + (lane << 1)];
        unsigned long long A1 = *(const unsigned long long*)&As[k * 128 + 64 + (lane << 1)];
        const ulonglong2* Bp = (const ulonglong2*)&Bs2[k * 128 + cbase];
#pragma unroll
        for (int j = 0; j < 8; j++) {
            ulonglong2 b = Bp[j];                  // {b2j,b2j},{b2j+1,b2j+1}
            fma2(acc0[2 * j],     A0, b.x);
            fma2(acc0[2 * j + 1], A0, b.y);
            fma2(acc1[2 * j],     A1, b.x);
            fma2(acc1[2 * j + 1], A1, b.y);
        }
    }

    // epilogue: 4 rows x 16 cols -> T16
    if (col0 + cbase + 16 <= NDB) {
#pragma unroll
        for (int h = 0; h < 2; h++) {
            const unsigned long long* ac = h ? acc1 : acc0;
#pragma unroll
            for (int rr = 0; rr < 2; rr++) {
                int row = row0 + h * 64 + (lane << 1) + rr;
                uint4 o0, o1;
                unsigned int w[8];
#pragma unroll
                for (int q = 0; q < 8; q++) {
                    float vlo = rr ? f32hi(ac[2 * q])     : f32lo(ac[2 * q]);
                    float vhi = rr ? f32hi(ac[2 * q + 1]) : f32lo(ac[2 * q + 1]);
                    w[q] = (mkey(vlo) >> 16) | (mkey(vhi) & 0xFFFF0000u);
                }
                o0.x = w[0]; o0.y = w[1]; o0.z = w[2]; o0.w = w[3];
                o1.x = w[4]; o1.y = w[5]; o1.z = w[6]; o1.w = w[7];
                uint4* dst = (uint4*)&g_T16[(size_t)row * NDB + col0 + cbase];
                dst[0] = o0;
                dst[1] = o1;
            }
        }
    }
}

// ---------------- K3: per-row 4096-bin histograms from g_T16 ----------------
__global__ void __launch_bounds__(512) k3_hist() {
    __shared__ unsigned int h[4096];
    int row  = blockIdx.y;
    int part = blockIdx.x;
    for (int i = threadIdx.x; i < 4096; i += 512) h[i] = 0u;
    __syncthreads();
    const uint4* Tp = (const uint4*)(g_T16 + (size_t)row * NDB) + (size_t)part * VP16;
#pragma unroll 2
    for (int i = threadIdx.x; i < VP16; i += 512) {
        uint4 v = Tp[i];
        atomicAdd(&h[(v.x & 0xFFFFu) >> 4], 1u);
        atomicAdd(&h[(v.x >> 20)],          1u);
        atomicAdd(&h[(v.y & 0xFFFFu) >> 4], 1u);
        atomicAdd(&h[(v.y >> 20)],          1u);
        atomicAdd(&h[(v.z & 0xFFFFu) >> 4], 1u);
        atomicAdd(&h[(v.z >> 20)],          1u);
        atomicAdd(&h[(v.w & 0xFFFFu) >> 4], 1u);
        atomicAdd(&h[(v.w >> 20)],          1u);
    }
    __syncthreads();
    unsigned int* gh = &g_hist[row * 4096];
    for (int i = threadIdx.x; i < 4096; i += 512)
        if (h[i]) atomicAdd(&gh[i], h[i]);
}

// ---------------- K3b: parallel suffix scan -> d1, need ----------------
__global__ void __launch_bounds__(256) k3b_scan() {
    __shared__ unsigned int part[256];
    int row = blockIdx.x;
    int t = threadIdx.x;
    const unsigned int* gh = &g_hist[row * 4096];
    unsigned int loc[16];
    unsigned int s = 0;
#pragma unroll
    for (int j = 0; j < 16; j++) { loc[j] = gh[t * 16 + j]; s += loc[j]; }
    part[t] = s;
    __syncthreads();
    for (int off = 1; off < 256; off <<= 1) {
        unsigned int add = (t + off < 256) ? part[t + off] : 0u;
        __syncthreads();
        part[t] += add;
        __syncthreads();
    }
    unsigned int sAbove = (t < 255) ? part[t + 1] : 0u;
    if (part[t] >= KSEL && sAbove < KSEL) {
        unsigned int cum = sAbove;
        for (int j = 15; j >= 0; j--) {
            cum += loc[j];
            if (cum >= KSEL) {
                g_d1[row]   = t * 16 + j;
                g_need[row] = KSEL - (int)(cum - loc[j]);
                break;
            }
        }
    }
}

// ---------------- K4: classify via T16; recompute exact dot for boundary only ----------------
__global__ void __launch_bounds__(512) k4_compact(const int* __restrict__ labels,
                                                  const float* __restrict__ codes) {
    __shared__ unsigned int lh[NCLS];
    __shared__ float arow[DIM];
    __shared__ int s_is64;
    int row  = blockIdx.y;
    int part = blockIdx.x;
    int d1   = g_d1[row];
    int lane = threadIdx.x & 31;
    if (threadIdx.x < NCLS) lh[threadIdx.x] = 0u;
    if (threadIdx.x < DIM)  arow[threadIdx.x] = g_outm[row * DIM + threadIdx.x];
    if (threadIdx.x == 0) s_is64 = probe_is64(labels);
    __syncthreads();
    int is64 = s_is64;

    const uint4* Tp = (const uint4*)(g_T16 + (size_t)row * NDB) + (size_t)part * VP16;
    unsigned long long* cp = &g_cand[(size_t)row * CANDCAP];
    int nbase = part * (VP16 * 8);

    for (int i0 = 0; i0 < VP16; i0 += 512) {
        int i = i0 + threadIdx.x;
        bool valid = (i < VP16);
        uint4 v = make_uint4(0, 0, 0, 0);
        if (valid) v = Tp[i];
        unsigned short s8[8];
        s8[0] = (unsigned short)(v.x & 0xFFFFu); s8[1] = (unsigned short)(v.x >> 16);
        s8[2] = (unsigned short)(v.y & 0xFFFFu); s8[3] = (unsigned short)(v.y >> 16);
        s8[4] = (unsigned short)(v.z & 0xFFFFu); s8[5] = (unsigned short)(v.z >> 16);
        s8[6] = (unsigned short)(v.w & 0xFFFFu); s8[7] = (unsigned short)(v.w >> 16);
        int n0 = nbase + i * 8;
#pragma unroll
        for (int e = 0; e < 8; e++) {
            int top = (int)(s8[e] >> 4);
            bool above = valid && (top > d1);
            bool bound = valid && (top == d1);
            if (above) {
                int l = ldlabel(labels, n0 + e, is64);
                if (l >= 0 && l < NCLS) atomicAdd(&lh[l], 1u);
            }
            unsigned int m = __ballot_sync(0xFFFFFFFFu, bound);
            if (m) {
                int leader = __ffs(m) - 1;
                unsigned int base = 0;
                if (lane == leader) base = atomicAdd(&g_candCnt[row], (unsigned int)__popc(m));
                base = __shfl_sync(0xFFFFFFFFu, base, leader);
                if (bound) {
                    int n = n0 + e;
                    const float* cd = codes + ((size_t)n << 6);
                    float accv = 0.f;
#pragma unroll
                    for (int k = 0; k < DIM; k++) accv = fmaf(arow[k], cd[k], accv);
                    unsigned int mk = mkey(accv);
                    int rank = __popc(m & ((1u << lane) - 1u));
                    unsigned int pos = base + rank;
                    if (pos < CANDCAP)
                        cp[pos] = ((unsigned long long)(mk & 0xFFFFFu) << 17) |
                                  (unsigned long long)(unsigned int)(131071 - n);
                }
            }
        }
    }
    __syncthreads();
    if (threadIdx.x < NCLS && lh[threadIdx.x])
        atomicAdd(&g_counts[row * NCLS + threadIdx.x], lh[threadIdx.x]);
}

// ---------------- K5: exact 3-stage radix select + finalize ----------------
__global__ void __launch_bounds__(512) k5_select(const int* __restrict__ labels,
                                                 float* __restrict__ out) {
    __shared__ unsigned int h[8192];
    __shared__ unsigned int part[512];
    __shared__ unsigned int lh[NCLS];
    __shared__ int s_dig, s_need, s_is64;
    int b = blockIdx.x;
    int t = threadIdx.x;
    int need = g_need[b];
    unsigned int cc = g_candCnt[b];
    if (cc > CANDCAP) cc = CANDCAP;
    const unsigned long long* cp = &g_cand[(size_t)b * CANDCAP];

    if (t == 0) s_is64 = probe_is64(labels);

    const int shifts[3] = {24, 12, 0};
    const int nbits[3]  = {13, 12, 12};
    unsigned long long prefix = 0ull;

    for (int s = 0; s < 3; s++) {
        int sh = shifts[s];
        int nb = 1 << nbits[s];
        int ch = nb >> 9;
        unsigned long long pmask = ~(((1ull << (sh + nbits[s])) - 1ull));
        for (int i = t; i < nb; i += 512) h[i] = 0u;
        __syncthreads();
        for (unsigned int i = t; i < cc; i += 512) {
            unsigned long long cv = cp[i];
            if ((cv & pmask) == prefix)
                atomicAdd(&h[(unsigned int)(cv >> sh) & (nb - 1)], 1u);
        }
        __syncthreads();
        unsigned int loc = 0;
        for (int j = 0; j < ch; j++) loc += h[t * ch + j];
        part[t] = loc;
        __syncthreads();
        for (int off = 1; off < 512; off <<= 1) {
            unsigned int add = (t + off < 512) ? part[t + off] : 0u;
            __syncthreads();
            part[t] += add;
            __syncthreads();
        }
        unsigned int sAbove = (t < 511) ? part[t + 1] : 0u;
        if ((int)part[t] >= need && (int)sAbove < need) {
            unsigned int cum = sAbove;
            for (int j = ch - 1; j >= 0; j--) {
                cum += h[t * ch + j];
                if ((int)cum >= need) {
                    s_dig  = t * ch + j;
                    s_need = need - (int)(cum - h[t * ch + j]);
                    break;
                }
            }
        }
        __syncthreads();
        prefix |= ((unsigned long long)s_dig) << sh;
        need = s_need;
        __syncthreads();
    }

    if (t < NCLS) lh[t] = 0u;
    __syncthreads();
    int is64 = s_is64;
    for (unsigned int i = t; i < cc; i += 512) {
        unsigned long long cv = cp[i];
        if (cv >= prefix) {
            int idx = 131071 - (int)(cv & 0x1FFFFull);
            if (idx >= 0 && idx < NDB) {
                int l = ldlabel(labels, idx, is64);
                if (l >= 0 && l < NCLS) atomicAdd(&lh[l], 1u);
            }
        }
    }
    __syncthreads();
    if (t < NCLS) {
        unsigned int tot = g_counts[b * NCLS + t] + lh[t];
        out[b * NCLS + t] = (float)tot * (1.0f / (float)KSEL);
    }
}

// ---------------- launch ----------------
extern "C" void kernel_launch(void* const* d_in, const int* in_sizes, int n_in,
                              void* d_out, int out_size) {
    const float* x      = (const float*)d_in[0];
    const float* W      = (const float*)d_in[1];
    const float* codes  = (const float*)d_in[2];
    const int*   labels = (const int*)d_in[3];
    float*       out    = (float*)d_out;

    cudaFuncSetAttribute(k2_gemm, cudaFuncAttributeMaxDynamicSharedMemorySize, S_K2TOT);

    z1_hist<<<NROWS * 4096 / (512 * 4), 512>>>();
    z2_misc<<<(NROWS * NCLS + 511) / 512, 512>>>();
    k1_proj<<<NROWS, 256>>>(x, W);
    dim3 g2(NROWS / 128, (NDB + 127) / 128);
    k2_gemm<<<g2, 256, S_K2TOT>>>(codes);        // launch #4 -> ncu samples this
    dim3 g3(SPLIT, NROWS);
    k3_hist<<<g3, 512>>>();
    k3b_scan<<<NROWS, 256>>>();
    k4_compact<<<g3, 512>>>(labels, codes);
    k5_select<<<NROWS, 512>>>(labels, out);
}

// round 9
// speedup vs baseline: 1.1135x; 1.1135x over previous
#include <cuda_runtime.h>
#include <cstdint>

#define NROWS 256
#define NDB   100000
#define DIM   64
#define XDIM  2048
#define NCLS  100
#define KSEL  1000
#define SPLIT 5
#define VP16  2500           // uint4 (8 u16) vectors per (row,part): 100000/8/5

// ---------------- static device scratch ----------------
__device__ float              g_outm[NROWS * DIM];
__device__ unsigned short     g_T16[(size_t)NROWS * NDB];               // 51.2 MB top-16 keys
__device__ unsigned long long g_cand[(size_t)NROWS * NDB / 8];          // 25.6 MB
__device__ unsigned int       g_hist[NROWS * 4096];
__device__ int                g_d1[NROWS];
__device__ int                g_need[NROWS];
__device__ unsigned int       g_candCnt[NROWS];
__device__ unsigned int       g_counts[NROWS * NCLS];

#define CANDCAP (NDB / 8)     // 12500 per row

// ---------------- helpers ----------------
__device__ __forceinline__ unsigned int mkey(float f) {
    unsigned int u = __float_as_uint(f);
    return (u & 0x80000000u) ? ~u : (u | 0x80000000u);
}
__device__ __forceinline__ unsigned long long pk(float lo, float hi) {
    unsigned long long r;
    asm("mov.b64 %0, {%1,%2};" : "=l"(r)
        : "r"(__float_as_uint(lo)), "r"(__float_as_uint(hi)));
    return r;
}
__device__ __forceinline__ void fma2(unsigned long long& d, unsigned long long a, unsigned long long b) {
    asm("fma.rn.f32x2 %0, %1, %2, %0;" : "+l"(d) : "l"(a), "l"(b));
}
__device__ __forceinline__ float f32lo(unsigned long long v) { return __uint_as_float((unsigned int)v); }
__device__ __forceinline__ float f32hi(unsigned long long v) { return __uint_as_float((unsigned int)(v >> 32)); }
__device__ __forceinline__ int probe_is64(const int* L) {
    int s = 0;
#pragma unroll
    for (int i = 1; i < 129; i += 2) s |= L[i];
    return (s == 0) ? 1 : 0;
}
__device__ __forceinline__ int ldlabel(const int* L, int n, int is64) {
    return is64 ? L[(size_t)2 * n] : L[n];
}

// ---------------- Z1/Z2: zero scratch ----------------
__global__ void __launch_bounds__(512) z1_hist() {
    ((uint4*)g_hist)[blockIdx.x * 512 + threadIdx.x] = make_uint4(0, 0, 0, 0);
}
__global__ void __launch_bounds__(512) z2_misc() {
    int i = blockIdx.x * 512 + threadIdx.x;
    if (i < NROWS * NCLS) g_counts[i] = 0u;
    if (i < NROWS) g_candCnt[i] = 0u;
}

// ---------------- K1: out = x @ W ----------------
__global__ void __launch_bounds__(256) k1_proj(const float* __restrict__ x,
                                               const float* __restrict__ W) {
    __shared__ __align__(16) float xs[XDIM];
    __shared__ float part[4][DIM];
    int b = blockIdx.x;
    const float4* xr = (const float4*)(x + (size_t)b * XDIM);
    for (int i = threadIdx.x; i < XDIM / 4; i += 256)
        ((float4*)xs)[i] = xr[i];
    __syncthreads();
    int j = threadIdx.x & 63;
    int p = threadIdx.x >> 6;
    const float* Wp = W + (size_t)(p * 512) * DIM + j;
    const float* xp = xs + p * 512;
    float a0 = 0.f, a1 = 0.f, a2 = 0.f, a3 = 0.f;
#pragma unroll 4
    for (int k = 0; k < 128; k++) {
        a0 += xp[k]       * Wp[(size_t)(k)       * DIM];
        a1 += xp[k + 128] * Wp[(size_t)(k + 128) * DIM];
        a2 += xp[k + 256] * Wp[(size_t)(k + 256) * DIM];
        a3 += xp[k + 384] * Wp[(size_t)(k + 384) * DIM];
    }
    part[p][j] = (a0 + a1) + (a2 + a3);
    __syncthreads();
    if (threadIdx.x < DIM)
        g_outm[b * DIM + threadIdx.x] =
            (part[0][threadIdx.x] + part[1][threadIdx.x]) +
            (part[2][threadIdx.x] + part[3][threadIdx.x]);
}

// ---------------- K2 v4: 128x128 tile; 8x8 per thread; 2B/lane/FFMA2 ----------------
// smem: As float[64][128] = 32KB ; Bs float[64][128] = 32KB (both k-major, NO duplication)
#define S_A 0
#define S_B 32768
#define S_K2TOT 65536

__global__ void __launch_bounds__(256, 2) k2_gemm(const float* __restrict__ codes) {
    extern __shared__ __align__(16) char smem[];
    float* As = (float*)(smem + S_A);                 // As[k*128 + row]
    float* Bs = (float*)(smem + S_B);                 // Bs[k*128 + col]
    const int tid  = threadIdx.x;
    const int wid  = tid >> 5;
    const int lane = tid & 31;
    const int row0 = blockIdx.x << 7;
    const int col0 = blockIdx.y << 7;

    // A tile: 128 rows x 64 k (k-major)
#pragma unroll
    for (int t = 0; t < 8; t++) {
        int e  = tid + t * 256;
        int r  = e >> 4;
        int k4 = (e & 15) << 2;
        float4 v = *(const float4*)&g_outm[((row0 + r) << 6) + k4];
#pragma unroll
        for (int j = 0; j < 4; j++)
            As[(k4 + j) * 128 + r] = (&v.x)[j];
    }
    // B tile: 128 cols x 64 k (k-major, plain floats)
#pragma unroll
    for (int t = 0; t < 8; t++) {
        int e  = tid + t * 256;
        int n  = e >> 4;
        int k4 = (e & 15) << 2;
        int gn = col0 + n;
        float4 v = make_float4(0.f, 0.f, 0.f, 0.f);
        if (gn < NDB) v = *(const float4*)&codes[((size_t)gn << 6) + k4];
#pragma unroll
        for (int j = 0; j < 4; j++)
            Bs[(k4 + j) * 128 + n] = (&v.x)[j];
    }
    __syncthreads();

    const int r0 = (lane & 15) << 3;                  // 8 consecutive rows
    const int c0 = (wid << 4) + ((lane >> 4) << 3);   // 8 consecutive cols
    unsigned long long acc[8][4];
#pragma unroll
    for (int r = 0; r < 8; r++)
#pragma unroll
        for (int c = 0; c < 4; c++) acc[r][c] = 0ull;

#pragma unroll 8
    for (int k = 0; k < 64; k++) {
        const float4* Ak = (const float4*)&As[k * 128 + r0];
        const float4* Bk = (const float4*)&Bs[k * 128 + c0];
        float4 a0 = Ak[0], a1 = Ak[1];
        float4 b0 = Bk[0], b1 = Bk[1];
        unsigned long long bp0 = pk(b0.x, b0.y);
        unsigned long long bp1 = pk(b0.z, b0.w);
        unsigned long long bp2 = pk(b1.x, b1.y);
        unsigned long long bp3 = pk(b1.z, b1.w);
        float ar[8] = {a0.x, a0.y, a0.z, a0.w, a1.x, a1.y, a1.z, a1.w};
#pragma unroll
        for (int r = 0; r < 8; r++) {
            unsigned long long ad = pk(ar[r], ar[r]);
            fma2(acc[r][0], ad, bp0);
            fma2(acc[r][1], ad, bp1);
            fma2(acc[r][2], ad, bp2);
            fma2(acc[r][3], ad, bp3);
        }
    }

    // epilogue: 8 rows x 8 cols -> one uint4 (8 u16) store per row
    if (col0 + c0 + 8 <= NDB) {
#pragma unroll
        for (int r = 0; r < 8; r++) {
            int row = row0 + r0 + r;
            uint4 o;
            o.x = (mkey(f32lo(acc[r][0])) >> 16) | (mkey(f32hi(acc[r][0])) & 0xFFFF0000u);
            o.y = (mkey(f32lo(acc[r][1])) >> 16) | (mkey(f32hi(acc[r][1])) & 0xFFFF0000u);
            o.z = (mkey(f32lo(acc[r][2])) >> 16) | (mkey(f32hi(acc[r][2])) & 0xFFFF0000u);
            o.w = (mkey(f32lo(acc[r][3])) >> 16) | (mkey(f32hi(acc[r][3])) & 0xFFFF0000u);
            *(uint4*)&g_T16[(size_t)row * NDB + col0 + c0] = o;
        }
    }
}

// ---------------- K3: per-row 4096-bin histograms from g_T16 ----------------
__global__ void __launch_bounds__(512) k3_hist() {
    __shared__ unsigned int h[4096];
    int row  = blockIdx.y;
    int part = blockIdx.x;
    for (int i = threadIdx.x; i < 4096; i += 512) h[i] = 0u;
    __syncthreads();
    const uint4* Tp = (const uint4*)(g_T16 + (size_t)row * NDB) + (size_t)part * VP16;
#pragma unroll 2
    for (int i = threadIdx.x; i < VP16; i += 512) {
        uint4 v = Tp[i];
        atomicAdd(&h[(v.x & 0xFFFFu) >> 4], 1u);
        atomicAdd(&h[(v.x >> 20)],          1u);
        atomicAdd(&h[(v.y & 0xFFFFu) >> 4], 1u);
        atomicAdd(&h[(v.y >> 20)],          1u);
        atomicAdd(&h[(v.z & 0xFFFFu) >> 4], 1u);
        atomicAdd(&h[(v.z >> 20)],          1u);
        atomicAdd(&h[(v.w & 0xFFFFu) >> 4], 1u);
        atomicAdd(&h[(v.w >> 20)],          1u);
    }
    __syncthreads();
    unsigned int* gh = &g_hist[row * 4096];
    for (int i = threadIdx.x; i < 4096; i += 512)
        if (h[i]) atomicAdd(&gh[i], h[i]);
}

// ---------------- K3b: parallel suffix scan -> d1, need ----------------
__global__ void __launch_bounds__(256) k3b_scan() {
    __shared__ unsigned int part[256];
    int row = blockIdx.x;
    int t = threadIdx.x;
    const unsigned int* gh = &g_hist[row * 4096];
    unsigned int loc[16];
    unsigned int s = 0;
#pragma unroll
    for (int j = 0; j < 16; j++) { loc[j] = gh[t * 16 + j]; s += loc[j]; }
    part[t] = s;
    __syncthreads();
    for (int off = 1; off < 256; off <<= 1) {
        unsigned int add = (t + off < 256) ? part[t + off] : 0u;
        __syncthreads();
        part[t] += add;
        __syncthreads();
    }
    unsigned int sAbove = (t < 255) ? part[t + 1] : 0u;
    if (part[t] >= KSEL && sAbove < KSEL) {
        unsigned int cum = sAbove;
        for (int j = 15; j >= 0; j--) {
            cum += loc[j];
            if (cum >= KSEL) {
                g_d1[row]   = t * 16 + j;
                g_need[row] = KSEL - (int)(cum - loc[j]);
                break;
            }
        }
    }
}

// ---------------- K4: classify via T16; recompute exact dot for boundary only ----------------
__global__ void __launch_bounds__(512) k4_compact(const int* __restrict__ labels,
                                                  const float* __restrict__ codes) {
    __shared__ unsigned int lh[NCLS];
    __shared__ float arow[DIM];
    __shared__ int s_is64;
    int row  = blockIdx.y;
    int part = blockIdx.x;
    int d1   = g_d1[row];
    int lane = threadIdx.x & 31;
    if (threadIdx.x < NCLS) lh[threadIdx.x] = 0u;
    if (threadIdx.x < DIM)  arow[threadIdx.x] = g_outm[row * DIM + threadIdx.x];
    if (threadIdx.x == 0) s_is64 = probe_is64(labels);
    __syncthreads();
    int is64 = s_is64;

    const uint4* Tp = (const uint4*)(g_T16 + (size_t)row * NDB) + (size_t)part * VP16;
    unsigned long long* cp = &g_cand[(size_t)row * CANDCAP];
    int nbase = part * (VP16 * 8);

    for (int i0 = 0; i0 < VP16; i0 += 512) {
        int i = i0 + threadIdx.x;
        bool valid = (i < VP16);
        uint4 v = make_uint4(0, 0, 0, 0);
        if (valid) v = Tp[i];
        unsigned short s8[8];
        s8[0] = (unsigned short)(v.x & 0xFFFFu); s8[1] = (unsigned short)(v.x >> 16);
        s8[2] = (unsigned short)(v.y & 0xFFFFu); s8[3] = (unsigned short)(v.y >> 16);
        s8[4] = (unsigned short)(v.z & 0xFFFFu); s8[5] = (unsigned short)(v.z >> 16);
        s8[6] = (unsigned short)(v.w & 0xFFFFu); s8[7] = (unsigned short)(v.w >> 16);
        int n0 = nbase + i * 8;
#pragma unroll
        for (int e = 0; e < 8; e++) {
            int top = (int)(s8[e] >> 4);
            bool above = valid && (top > d1);
            bool bound = valid && (top == d1);
            if (above) {
                int l = ldlabel(labels, n0 + e, is64);
                if (l >= 0 && l < NCLS) atomicAdd(&lh[l], 1u);
            }
            unsigned int m = __ballot_sync(0xFFFFFFFFu, bound);
            if (m) {
                int leader = __ffs(m) - 1;
                unsigned int base = 0;
                if (lane == leader) base = atomicAdd(&g_candCnt[row], (unsigned int)__popc(m));
                base = __shfl_sync(0xFFFFFFFFu, base, leader);
                if (bound) {
                    int n = n0 + e;
                    const float* cd = codes + ((size_t)n << 6);
                    float accv = 0.f;
#pragma unroll
                    for (int k = 0; k < DIM; k++) accv = fmaf(arow[k], cd[k], accv);
                    unsigned int mk = mkey(accv);
                    int rank = __popc(m & ((1u << lane) - 1u));
                    unsigned int pos = base + rank;
                    if (pos < CANDCAP)
                        cp[pos] = ((unsigned long long)(mk & 0xFFFFFu) << 17) |
                                  (unsigned long long)(unsigned int)(131071 - n);
                }
            }
        }
    }
    __syncthreads();
    if (threadIdx.x < NCLS && lh[threadIdx.x])
        atomicAdd(&g_counts[row * NCLS + threadIdx.x], lh[threadIdx.x]);
}

// ---------------- K5: exact 3-stage radix select + finalize ----------------
__global__ void __launch_bounds__(512) k5_select(const int* __restrict__ labels,
                                                 float* __restrict__ out) {
    __shared__ unsigned int h[8192];
    __shared__ unsigned int part[512];
    __shared__ unsigned int lh[NCLS];
    __shared__ int s_dig, s_need, s_is64;
    int b = blockIdx.x;
    int t = threadIdx.x;
    int need = g_need[b];
    unsigned int cc = g_candCnt[b];
    if (cc > CANDCAP) cc = CANDCAP;
    const unsigned long long* cp = &g_cand[(size_t)b * CANDCAP];

    if (t == 0) s_is64 = probe_is64(labels);

    const int shifts[3] = {24, 12, 0};
    const int nbits[3]  = {13, 12, 12};
    unsigned long long prefix = 0ull;

    for (int s = 0; s < 3; s++) {
        int sh = shifts[s];
        int nb = 1 << nbits[s];
        int ch = nb >> 9;
        unsigned long long pmask = ~(((1ull << (sh + nbits[s])) - 1ull));
        for (int i = t; i < nb; i += 512) h[i] = 0u;
        __syncthreads();
        for (unsigned int i = t; i < cc; i += 512) {
            unsigned long long cv = cp[i];
            if ((cv & pmask) == prefix)
                atomicAdd(&h[(unsigned int)(cv >> sh) & (nb - 1)], 1u);
        }
        __syncthreads();
        unsigned int loc = 0;
        for (int j = 0; j < ch; j++) loc += h[t * ch + j];
        part[t] = loc;
        __syncthreads();
        for (int off = 1; off < 512; off <<= 1) {
            unsigned int add = (t + off < 512) ? part[t + off] : 0u;
            __syncthreads();
            part[t] += add;
            __syncthreads();
        }
        unsigned int sAbove = (t < 511) ? part[t + 1] : 0u;
        if ((int)part[t] >= need && (int)sAbove < need) {
            unsigned int cum = sAbove;
            for (int j = ch - 1; j >= 0; j--) {
                cum += h[t * ch + j];
                if ((int)cum >= need) {
                    s_dig  = t * ch + j;
                    s_need = need - (int)(cum - h[t * ch + j]);
                    break;
                }
            }
        }
        __syncthreads();
        prefix |= ((unsigned long long)s_dig) << sh;
        need = s_need;
        __syncthreads();
    }

    if (t < NCLS) lh[t] = 0u;
    __syncthreads();
    int is64 = s_is64;
    for (unsigned int i = t; i < cc; i += 512) {
        unsigned long long cv = cp[i];
        if (cv >= prefix) {
            int idx = 131071 - (int)(cv & 0x1FFFFull);
            if (idx >= 0 && idx < NDB) {
                int l = ldlabel(labels, idx, is64);
                if (l >= 0 && l < NCLS) atomicAdd(&lh[l], 1u);
            }
        }
    }
    __syncthreads();
    if (t < NCLS) {
        unsigned int tot = g_counts[b * NCLS + t] + lh[t];
        out[b * NCLS + t] = (float)tot * (1.0f / (float)KSEL);
    }
}

// ---------------- launch ----------------
extern "C" void kernel_launch(void* const* d_in, const int* in_sizes, int n_in,
                              void* d_out, int out_size) {
    const float* x      = (const float*)d_in[0];
    const float* W      = (const float*)d_in[1];
    const float* codes  = (const float*)d_in[2];
    const int*   labels = (const int*)d_in[3];
    float*       out    = (float*)d_out;

    cudaFuncSetAttribute(k2_gemm, cudaFuncAttributeMaxDynamicSharedMemorySize, S_K2TOT);

    z1_hist<<<NROWS * 4096 / (512 * 4), 512>>>();
    z2_misc<<<(NROWS * NCLS + 511) / 512, 512>>>();
    k1_proj<<<NROWS, 256>>>(x, W);
    dim3 g2(NROWS / 128, (NDB + 127) / 128);
    k2_gemm<<<g2, 256, S_K2TOT>>>(codes);        // launch #4 -> ncu samples this
    dim3 g3(SPLIT, NROWS);
    k3_hist<<<g3, 512>>>();
    k3b_scan<<<NROWS, 256>>>();
    k4_compact<<<g3, 512>>>(labels, codes);
    k5_select<<<NROWS, 512>>>(labels, out);
}